// round 7
// baseline (speedup 1.0000x reference)
#include <cuda_runtime.h>
#include <cuda_fp16.h>
#include <math_constants.h>

#define SS 4096
#define II 1024
#define CC 8
#define HH 8
#define SBLK (SS/32)

typedef unsigned long long u64;

// ---- scratch ----
__device__ __half2 g_kw[(size_t)II*SS];       // (k, w=exp(bias)) per [i][s]
__device__ float   g_v [(size_t)II*SS];       // v [i][s]
__device__ uint4   g_g [(size_t)SS*II];       // gate: 8 fp16 per (s,i), [s][i] layout
__device__ float   g_qpart[(size_t)SBLK*II*9];
__device__ float   g_o[(size_t)II*HH];

// ---- f32x2 helpers ----
__device__ __forceinline__ u64 pk2(float lo, float hi){u64 r;asm("mov.b64 %0,{%1,%2};":"=l"(r):"f"(lo),"f"(hi));return r;}
__device__ __forceinline__ void un2(u64 v, float&a, float&b){asm("mov.b64 {%0,%1},%2;":"=f"(a),"=f"(b):"l"(v));}
__device__ __forceinline__ u64 f2fma(u64 a,u64 b,u64 c){u64 d;asm("fma.rn.f32x2 %0,%1,%2,%3;":"=l"(d):"l"(a),"l"(b),"l"(c));return d;}
__device__ __forceinline__ u64 f2mul(u64 a,u64 b){u64 d;asm("mul.rn.f32x2 %0,%1,%2;":"=l"(d):"l"(a),"l"(b));return d;}
__device__ __forceinline__ float tanha(float x){float r;asm("tanh.approx.f32 %0,%1;":"=f"(r):"f"(x));return r;}

// ============================================================
// K1: LayerNorm + (k,w)/v planes (transposed) + gate (fp16,[s][i])
//     + q-pool partials.  Row-pair-at-a-time to cap registers.
// grid (II/32, SS/32), block 256
// ============================================================
__global__ __launch_bounds__(256,3) void k1_kernel(
    const float* __restrict__ m, const float* __restrict__ mask,
    const float* __restrict__ gamma, const float* __restrict__ beta,
    const float* __restrict__ Wk, const float* __restrict__ Wv,
    const float* __restrict__ Wg, const float* __restrict__ bg)
{
    __shared__ float tk[32][33], tv[32][33], tw[32][33];
    __shared__ float red[3][8][33];
    __shared__ float wgt[32];
    __shared__ ulonglong2 sGW[8][4];   // dup gamma*Wg pairs
    __shared__ u64 sNW[8];             // dup -sum_c gamma_c*Wg[c,h]
    __shared__ u64 sCB2[8];            // dup 0.5*(beta@Wg[:,h]+bg_h)

    int tid = threadIdx.x;
    if (tid < 32) {
        float v;
        if      (tid <  8) v = gamma[tid];
        else if (tid < 16) v = beta[tid-8];
        else if (tid < 24) v = Wk[tid-16];
        else               v = Wv[tid-24];
        wgt[tid] = v;
    } else if (tid < 64) {
        int t = tid - 32; int h = t >> 2, cp = t & 3;
        float w0 = gamma[2*cp]  * Wg[(2*cp)*8 + h];
        float w1 = gamma[2*cp+1]* Wg[(2*cp+1)*8 + h];
        sGW[h][cp] = make_ulonglong2(pk2(w0,w0), pk2(w1,w1));
    } else if (tid < 72) {
        int h = tid - 64;
        float ws = 0.f, cb = 0.f;
        #pragma unroll
        for (int c = 0; c < 8; c++) {
            ws += gamma[c]*Wg[c*8+h];
            cb += beta[c] *Wg[c*8+h];
        }
        cb += bg[h];
        sNW[h]  = pk2(-ws, -ws);
        sCB2[h] = pk2(0.5f*cb, 0.5f*cb);
    }
    __syncthreads();

    int il = tid & 31, wp = tid >> 5;
    int i  = blockIdx.x*32 + il;
    int s0 = blockIdx.y*32;
    int sb = s0 + wp*4;

    // front-batched streaming loads (never re-read: .cs)
    float4 A[4][2];
    float mk[4];
    #pragma unroll
    for (int r = 0; r < 4; r++) {
        const float4* p = reinterpret_cast<const float4*>(m + ((size_t)(sb+r)*II + i)*CC);
        A[r][0] = __ldcs(p); A[r][1] = __ldcs(p+1);
    }
    #pragma unroll
    for (int r = 0; r < 4; r++) mk[r] = __ldcs(&mask[(size_t)(sb+r)*II + i]);

    float qacc[8];
    #pragma unroll
    for (int c = 0; c < 8; c++) qacc[c] = 0.f;
    float macc = 0.f;

    // -------- per row-pair: LN + k/v/q + gate, then release regs --------
    #pragma unroll
    for (int p = 0; p < 2; p++) {
        float muP[2], rsP[2];
        #pragma unroll
        for (int rr = 0; rr < 2; rr++) {
            int r = 2*p + rr;
            int sl = wp*4 + r;
            const float* x = &A[r][0].x;   // A[r][0..1] contiguous
            float mu = 0.f;
            #pragma unroll
            for (int c = 0; c < 8; c++) mu += x[c];
            mu *= 0.125f;
            float var = 0.f;
            #pragma unroll
            for (int c = 0; c < 8; c++) { float d = x[c]-mu; var += d*d; }
            var *= 0.125f;
            float rstd = rsqrtf(var + 1e-5f);
            muP[rr] = mu; rsP[rr] = rstd;
            float kv = 0.f, vv = 0.f;
            #pragma unroll
            for (int c = 0; c < 8; c++) {
                float mn = (x[c]-mu)*rstd*wgt[c] + wgt[8+c];
                kv += mn*wgt[16+c];
                vv += mn*wgt[24+c];
                qacc[c] += mn*mk[r];
            }
            macc += mk[r];
            tk[il][sl] = kv;
            tv[il][sl] = vv;
            tw[il][sl] = __expf(1e9f*(mk[r] - 1.f));
        }

        // gate for this pair (f32x2 across the two rows)
        u64 xp[8];
        #pragma unroll
        for (int c = 0; c < 4; c++) {
            xp[c]   = pk2((&A[2*p][0].x)[c], (&A[2*p+1][0].x)[c]);
            xp[4+c] = pk2((&A[2*p][1].x)[c], (&A[2*p+1][1].x)[c]);
        }
        u64 mu2 = pk2(muP[0], muP[1]);
        u64 h2r = pk2(0.5f*rsP[0], 0.5f*rsP[1]);
        unsigned gp0[4], gp1[4];
        float pr0, pr1;
        #pragma unroll
        for (int h = 0; h < 8; h++) {
            ulonglong2 w0 = sGW[h][0], w1 = sGW[h][1], w2 = sGW[h][2], w3 = sGW[h][3];
            u64 dot = f2mul(xp[0], w0.x);
            dot = f2fma(xp[1], w0.y, dot);
            dot = f2fma(xp[2], w1.x, dot);
            dot = f2fma(xp[3], w1.y, dot);
            dot = f2fma(xp[4], w2.x, dot);
            dot = f2fma(xp[5], w2.y, dot);
            dot = f2fma(xp[6], w3.x, dot);
            dot = f2fma(xp[7], w3.y, dot);
            u64 t  = f2fma(mu2, sNW[h], dot);    // dot - mu*ws
            u64 z2 = f2fma(h2r, t, sCB2[h]);     // 0.5*z
            float za, zb; un2(z2, za, zb);
            float ga = fmaf(0.5f, tanha(za), 0.5f);
            float gb = fmaf(0.5f, tanha(zb), 0.5f);
            if (h & 1) {
                __half2 ha = __floats2half2_rn(pr0, ga);
                __half2 hb = __floats2half2_rn(pr1, gb);
                gp0[h>>1] = *reinterpret_cast<unsigned*>(&ha);
                gp1[h>>1] = *reinterpret_cast<unsigned*>(&hb);
            } else {
                pr0 = ga; pr1 = gb;
            }
        }
        g_g[(size_t)(sb+2*p)*II + i]   = make_uint4(gp0[0], gp0[1], gp0[2], gp0[3]);
        g_g[(size_t)(sb+2*p+1)*II + i] = make_uint4(gp1[0], gp1[1], gp1[2], gp1[3]);
    }
    __syncthreads();

    // coalesced transposed writeout (scratch stays L2-resident for K2)
    {
        int ir = tid >> 3, sj = (tid & 7)*4;
        size_t off = (size_t)(blockIdx.x*32 + ir)*SS + s0 + sj;
        *reinterpret_cast<float4*>(g_v + off) =
            make_float4(tv[ir][sj], tv[ir][sj+1], tv[ir][sj+2], tv[ir][sj+3]);
        __half2 h0 = __floats2half2_rn(tk[ir][sj],   tw[ir][sj]);
        __half2 h1 = __floats2half2_rn(tk[ir][sj+1], tw[ir][sj+1]);
        __half2 h2 = __floats2half2_rn(tk[ir][sj+2], tw[ir][sj+2]);
        __half2 h3 = __floats2half2_rn(tk[ir][sj+3], tw[ir][sj+3]);
        uint4 u;
        u.x = *reinterpret_cast<unsigned int*>(&h0);
        u.y = *reinterpret_cast<unsigned int*>(&h1);
        u.z = *reinterpret_cast<unsigned int*>(&h2);
        u.w = *reinterpret_cast<unsigned int*>(&h3);
        *reinterpret_cast<uint4*>(g_kw + off) = u;
    }

    #pragma unroll
    for (int r = 0; r < 3; r++) {
        __syncthreads();
        #pragma unroll
        for (int gch = 0; gch < 3; gch++) {
            int c = r*3 + gch;
            red[gch][wp][il] = (c < 8) ? qacc[c] : macc;
        }
        __syncthreads();
        if (wp < 3) {
            int c = r*3 + wp;
            float sum = 0.f;
            #pragma unroll
            for (int w = 0; w < 8; w++) sum += red[wp][w][il];
            g_qpart[((size_t)blockIdx.y*II + i)*9 + c] = sum;
        }
    }
}

// ---------------- block reduction ----------------
__device__ __forceinline__ float warp_sum(float v) {
    #pragma unroll
    for (int o = 16; o; o >>= 1) v += __shfl_xor_sync(0xffffffffu, v, o);
    return v;
}
template<int N>
__device__ __forceinline__ void block_sum(float* vals, float* buf) {
    int lane = threadIdx.x & 31, wp = threadIdx.x >> 5;
    __syncthreads();
    #pragma unroll
    for (int n = 0; n < N; n++) {
        float v = warp_sum(vals[n]);
        if (lane == 0) buf[wp*N + n] = v;
    }
    __syncthreads();
    if (threadIdx.x < N) {
        float r = buf[threadIdx.x];
        #pragma unroll
        for (int w = 1; w < 8; w++) r += buf[w*N + threadIdx.x];
        buf[8*N + threadIdx.x] = r;
    }
    __syncthreads();
    #pragma unroll
    for (int n = 0; n < N; n++) vals[n] = buf[8*N + n];
}

// ============================================================
// K2: per-column q + softmax over s; scratch reads evict-first
// (dead afterwards) so the g plane stays L2-resident for K3.
// ============================================================
__global__ __launch_bounds__(256) void k2_kernel(const float* __restrict__ Wq)
{
    __shared__ float buf[9*16];
    __shared__ float swq[64];
    int tid = threadIdx.x;
    int i = blockIdx.x;
    if (tid < 64) swq[tid] = Wq[tid];

    float part[9];
    #pragma unroll
    for (int c = 0; c < 9; c++) part[c] = 0.f;
    if (tid < SBLK) {
        const float* p = g_qpart + ((size_t)tid*II + i)*9;
        #pragma unroll
        for (int c = 0; c < 9; c++) part[c] = __ldcs(p + c);
    }
    block_sum<9>(part, buf);

    float inv = 1.f/(part[8] + 1e-5f);
    float q[8];
    #pragma unroll
    for (int h = 0; h < 8; h++) {
        float s = 0.f;
        #pragma unroll
        for (int c = 0; c < 8; c++) s += (part[c]*inv)*swq[c*8 + h];
        q[h] = s;
    }

    const __half2* kwp = g_kw + (size_t)i*SS + tid*16;
    const float*   vp  = g_v  + (size_t)i*SS + tid*16;

    float so[16];
    #pragma unroll
    for (int n = 0; n < 16; n++) so[n] = 0.f;

    #pragma unroll
    for (int g = 0; g < 4; g++) {
        uint4 kw4 = __ldcs(reinterpret_cast<const uint4*>(kwp) + g);
        float4 vq = __ldcs(reinterpret_cast<const float4*>(vp) + g);
        unsigned kwu[4] = {kw4.x, kw4.y, kw4.z, kw4.w};
        float vv[4] = {vq.x, vq.y, vq.z, vq.w};
        #pragma unroll
        for (int e = 0; e < 4; e++) {
            float2 kw = __half22float2(*reinterpret_cast<__half2*>(&kwu[e]));
            float kk = kw.x, w = kw.y;
            #pragma unroll
            for (int h = 0; h < 8; h++) {
                float ex = w * __expf(q[h]*kk);
                so[h]   += ex;
                so[8+h] = fmaf(ex, vv[e], so[8+h]);
            }
        }
    }
    block_sum<16>(so, buf);

    if (tid < 8) g_o[(size_t)i*8 + tid] = so[8+tid] / so[tid];
}

// ============================================================
// K3: out = (oh .* g) @ Wo + bo.  Reads the fp16 gate plane
// (largely L2-resident) + tiny oh; writes out evict-first.
// ============================================================
__global__ __launch_bounds__(256) void k3_kernel(
    const float* __restrict__ Wo, const float* __restrict__ bo,
    float* __restrict__ out)
{
    __shared__ ulonglong2 sWO[8][4];
    __shared__ u64 sBO[8];

    int tid = threadIdx.x;
    if (tid < 32) {
        int h = tid >> 2, cp = tid & 3;
        float w0 = Wo[h*8 + 2*cp], w1 = Wo[h*8 + 2*cp+1];
        sWO[h][cp] = make_ulonglong2(pk2(w0,w0), pk2(w1,w1));
    } else if (tid < 40) {
        int c = tid - 32;
        sBO[c] = pk2(bo[c], bo[c]);
    }

    int il = tid & 31, wp = tid >> 5;
    int i  = blockIdx.x*32 + il;
    int s0 = (gridDim.y - 1 - blockIdx.y)*32;   // tail-first: ride K1's freshest g
    int sb = s0 + wp*4;

    float oh[8];
    {
        const float4* po = reinterpret_cast<const float4*>(g_o + (size_t)i*8);
        float4 a = po[0], b4 = po[1];
        oh[0]=a.x; oh[1]=a.y; oh[2]=a.z; oh[3]=a.w;
        oh[4]=b4.x; oh[5]=b4.y; oh[6]=b4.z; oh[7]=b4.w;
    }

    uint4 G[4];
    #pragma unroll
    for (int r = 0; r < 4; r++) G[r] = g_g[(size_t)(sb+r)*II + i];
    __syncthreads();

    float tf[4][8];
    #pragma unroll
    for (int r = 0; r < 4; r++) {
        unsigned uu[4] = {G[r].x, G[r].y, G[r].z, G[r].w};
        #pragma unroll
        for (int j = 0; j < 4; j++) {
            float2 f = __half22float2(*reinterpret_cast<__half2*>(&uu[j]));
            tf[r][2*j]   = oh[2*j]   * f.x;
            tf[r][2*j+1] = oh[2*j+1] * f.y;
        }
    }
    u64 th[2][8];
    #pragma unroll
    for (int p = 0; p < 2; p++)
        #pragma unroll
        for (int h = 0; h < 8; h++) th[p][h] = pk2(tf[2*p][h], tf[2*p+1][h]);

    u64 acc[2][8];
    #pragma unroll
    for (int c = 0; c < 8; c++) {
        u64 b = sBO[c];
        acc[0][c] = b; acc[1][c] = b;
    }

    #pragma unroll
    for (int h = 0; h < 8; h++) {
        ulonglong2 o0 = sWO[h][0], o1 = sWO[h][1], o2 = sWO[h][2], o3 = sWO[h][3];
        #pragma unroll
        for (int p = 0; p < 2; p++) {
            acc[p][0] = f2fma(th[p][h], o0.x, acc[p][0]);
            acc[p][1] = f2fma(th[p][h], o0.y, acc[p][1]);
            acc[p][2] = f2fma(th[p][h], o1.x, acc[p][2]);
            acc[p][3] = f2fma(th[p][h], o1.y, acc[p][3]);
            acc[p][4] = f2fma(th[p][h], o2.x, acc[p][4]);
            acc[p][5] = f2fma(th[p][h], o2.y, acc[p][5]);
            acc[p][6] = f2fma(th[p][h], o3.x, acc[p][6]);
            acc[p][7] = f2fma(th[p][h], o3.y, acc[p][7]);
        }
    }

    #pragma unroll
    for (int p = 0; p < 2; p++) {
        float y0[8], y1[8];
        #pragma unroll
        for (int c = 0; c < 8; c++) un2(acc[p][c], y0[c], y1[c]);
        size_t off0 = ((size_t)(sb+2*p)*II + i)*CC;
        size_t off1 = ((size_t)(sb+2*p+1)*II + i)*CC;
        __stcs(reinterpret_cast<float4*>(out + off0),     make_float4(y0[0],y0[1],y0[2],y0[3]));
        __stcs(reinterpret_cast<float4*>(out + off0 + 4), make_float4(y0[4],y0[5],y0[6],y0[7]));
        __stcs(reinterpret_cast<float4*>(out + off1),     make_float4(y1[0],y1[1],y1[2],y1[3]));
        __stcs(reinterpret_cast<float4*>(out + off1 + 4), make_float4(y1[4],y1[5],y1[6],y1[7]));
    }
}

// ============================================================
extern "C" void kernel_launch(void* const* d_in, const int* in_sizes, int n_in,
                              void* d_out, int out_size)
{
    const float* m     = (const float*)d_in[0];
    const float* mask  = (const float*)d_in[1];
    const float* gamma = (const float*)d_in[2];
    const float* beta  = (const float*)d_in[3];
    const float* Wq    = (const float*)d_in[4];
    const float* Wk    = (const float*)d_in[5];
    const float* Wv    = (const float*)d_in[6];
    const float* Wg    = (const float*)d_in[7];
    const float* bg    = (const float*)d_in[8];
    const float* Wo    = (const float*)d_in[9];
    const float* bo    = (const float*)d_in[10];
    float* out = (float*)d_out;

    dim3 g1(II/32, SS/32);
    k1_kernel<<<g1, 256>>>(m, mask, gamma, beta, Wk, Wv, Wg, bg);
    k2_kernel<<<II, 256>>>(Wq);
    dim3 g3(II/32, SS/32);
    k3_kernel<<<g3, 256>>>(Wo, bo, out);
}

// round 8
// speedup vs baseline: 1.5913x; 1.5913x over previous
#include <cuda_runtime.h>
#include <cuda_fp16.h>
#include <math_constants.h>

#define SS 4096
#define II 1024
#define CC 8
#define HH 8
#define SBLK (SS/32)

typedef unsigned long long u64;

// ---- scratch ----
__device__ __half2 g_kw[(size_t)II*SS];       // (k, w=exp(bias)) per [i][s]
__device__ float   g_v [(size_t)II*SS];       // v [i][s]
__device__ uint4   g_g [(size_t)SS*II];       // gate: 8 fp16 per (s,i), [s][i] layout
__device__ float   g_qpart[(size_t)SBLK*II*9];
__device__ float   g_o[(size_t)II*HH];

// ---- helpers ----
__device__ __forceinline__ u64 pk2(float lo, float hi){u64 r;asm("mov.b64 %0,{%1,%2};":"=l"(r):"f"(lo),"f"(hi));return r;}
__device__ __forceinline__ void un2(u64 v, float&a, float&b){asm("mov.b64 {%0,%1},%2;":"=f"(a),"=f"(b):"l"(v));}
__device__ __forceinline__ u64 f2fma(u64 a,u64 b,u64 c){u64 d;asm("fma.rn.f32x2 %0,%1,%2,%3;":"=l"(d):"l"(a),"l"(b),"l"(c));return d;}
__device__ __forceinline__ float tanha(float x){float r;asm("tanh.approx.f32 %0,%1;":"=f"(r):"f"(x));return r;}

// ============================================================
// K1: LayerNorm + (k,w)/v planes (transposed) + scalar gate
//     (fp16, [s][i]) + q-pool partials.  Small live set: gate
//     uses raw x regs + broadcast smem weights, no mn/xp arrays.
// grid (II/32, SS/32), block 256
// ============================================================
__global__ __launch_bounds__(256,3) void k1_kernel(
    const float* __restrict__ m, const float* __restrict__ mask,
    const float* __restrict__ gamma, const float* __restrict__ beta,
    const float* __restrict__ Wk, const float* __restrict__ Wv,
    const float* __restrict__ Wg, const float* __restrict__ bg)
{
    __shared__ float tk[32][33], tv[32][33], tw[32][33];
    __shared__ float red[3][8][33];
    __shared__ float wgt[32];
    __shared__ float sGWT[8][8];   // [h][c] = gamma[c]*Wg[c*8+h]
    __shared__ float sNW[8];       // -sum_c gamma_c*Wg[c,h]
    __shared__ float sCB2[8];      // 0.5*(beta@Wg[:,h] + bg_h)

    int tid = threadIdx.x;
    if (tid < 32) {
        float v;
        if      (tid <  8) v = gamma[tid];
        else if (tid < 16) v = beta[tid-8];
        else if (tid < 24) v = Wk[tid-16];
        else               v = Wv[tid-24];
        wgt[tid] = v;
    } else if (tid < 96) {
        int t = tid - 32; int h = t >> 3, c = t & 7;
        sGWT[h][c] = gamma[c] * Wg[c*8 + h];
    } else if (tid < 104) {
        int h = tid - 96;
        float ws = 0.f, cb = 0.f;
        #pragma unroll
        for (int c = 0; c < 8; c++) {
            ws += gamma[c]*Wg[c*8+h];
            cb += beta[c] *Wg[c*8+h];
        }
        cb += bg[h];
        sNW[h]  = -ws;
        sCB2[h] = 0.5f*cb;
    }
    __syncthreads();

    int il = tid & 31, wp = tid >> 5;
    int i  = blockIdx.x*32 + il;
    int s0 = blockIdx.y*32;
    int sb = s0 + wp*4;

    // front-batched streaming loads (never re-read: .cs)
    float4 A[4][2];
    float mk[4];
    #pragma unroll
    for (int r = 0; r < 4; r++) {
        const float4* p = reinterpret_cast<const float4*>(m + ((size_t)(sb+r)*II + i)*CC);
        A[r][0] = __ldcs(p); A[r][1] = __ldcs(p+1);
    }
    #pragma unroll
    for (int r = 0; r < 4; r++) mk[r] = __ldcs(&mask[(size_t)(sb+r)*II + i]);

    float qacc[8];
    #pragma unroll
    for (int c = 0; c < 8; c++) qacc[c] = 0.f;
    float macc = 0.f;

    #pragma unroll
    for (int r = 0; r < 4; r++) {
        int sl = wp*4 + r;
        const float* x = &A[r][0].x;     // A[r][0..1] contiguous 8 floats
        float mu = 0.f;
        #pragma unroll
        for (int c = 0; c < 8; c++) mu += x[c];
        mu *= 0.125f;
        float var = 0.f;
        #pragma unroll
        for (int c = 0; c < 8; c++) { float d = x[c]-mu; var += d*d; }
        var *= 0.125f;
        float rstd = rsqrtf(var + 1e-5f);
        float kv = 0.f, vv = 0.f;
        #pragma unroll
        for (int c = 0; c < 8; c++) {
            float mn = (x[c]-mu)*rstd*wgt[c] + wgt[8+c];
            kv += mn*wgt[16+c];
            vv += mn*wgt[24+c];
            qacc[c] += mn*mk[r];
        }
        macc += mk[r];
        tk[il][sl] = kv;
        tv[il][sl] = vv;
        tw[il][sl] = __expf(1e9f*(mk[r] - 1.f));

        // ---- scalar gate for this row; packs die immediately ----
        unsigned gp[4];
        float prev;
        float hr = 0.5f*rstd;
        #pragma unroll
        for (int h = 0; h < 8; h++) {
            const float4* wrow = reinterpret_cast<const float4*>(sGWT[h]);
            float4 w0 = wrow[0], w1 = wrow[1];
            float dot = x[0]*w0.x;
            dot = fmaf(x[1], w0.y, dot);
            dot = fmaf(x[2], w0.z, dot);
            dot = fmaf(x[3], w0.w, dot);
            dot = fmaf(x[4], w1.x, dot);
            dot = fmaf(x[5], w1.y, dot);
            dot = fmaf(x[6], w1.z, dot);
            dot = fmaf(x[7], w1.w, dot);
            float t  = fmaf(mu, sNW[h], dot);    // dot - mu*ws
            float z2 = fmaf(hr, t, sCB2[h]);     // 0.5*z
            float g  = fmaf(0.5f, tanha(z2), 0.5f);
            if (h & 1) {
                __half2 hh = __floats2half2_rn(prev, g);
                gp[h>>1] = *reinterpret_cast<unsigned*>(&hh);
            } else prev = g;
        }
        g_g[(size_t)(sb+r)*II + i] = make_uint4(gp[0], gp[1], gp[2], gp[3]);
    }
    __syncthreads();

    // coalesced transposed writeout (scratch stays L2-resident for K2)
    {
        int ir = tid >> 3, sj = (tid & 7)*4;
        size_t off = (size_t)(blockIdx.x*32 + ir)*SS + s0 + sj;
        *reinterpret_cast<float4*>(g_v + off) =
            make_float4(tv[ir][sj], tv[ir][sj+1], tv[ir][sj+2], tv[ir][sj+3]);
        __half2 h0 = __floats2half2_rn(tk[ir][sj],   tw[ir][sj]);
        __half2 h1 = __floats2half2_rn(tk[ir][sj+1], tw[ir][sj+1]);
        __half2 h2 = __floats2half2_rn(tk[ir][sj+2], tw[ir][sj+2]);
        __half2 h3 = __floats2half2_rn(tk[ir][sj+3], tw[ir][sj+3]);
        uint4 u;
        u.x = *reinterpret_cast<unsigned int*>(&h0);
        u.y = *reinterpret_cast<unsigned int*>(&h1);
        u.z = *reinterpret_cast<unsigned int*>(&h2);
        u.w = *reinterpret_cast<unsigned int*>(&h3);
        *reinterpret_cast<uint4*>(g_kw + off) = u;
    }

    #pragma unroll
    for (int r = 0; r < 3; r++) {
        __syncthreads();
        #pragma unroll
        for (int gch = 0; gch < 3; gch++) {
            int c = r*3 + gch;
            red[gch][wp][il] = (c < 8) ? qacc[c] : macc;
        }
        __syncthreads();
        if (wp < 3) {
            int c = r*3 + wp;
            float sum = 0.f;
            #pragma unroll
            for (int w = 0; w < 8; w++) sum += red[wp][w][il];
            g_qpart[((size_t)blockIdx.y*II + i)*9 + c] = sum;
        }
    }
}

// ---------------- block reduction ----------------
__device__ __forceinline__ float warp_sum(float v) {
    #pragma unroll
    for (int o = 16; o; o >>= 1) v += __shfl_xor_sync(0xffffffffu, v, o);
    return v;
}
template<int N>
__device__ __forceinline__ void block_sum(float* vals, float* buf) {
    int lane = threadIdx.x & 31, wp = threadIdx.x >> 5;
    __syncthreads();
    #pragma unroll
    for (int n = 0; n < N; n++) {
        float v = warp_sum(vals[n]);
        if (lane == 0) buf[wp*N + n] = v;
    }
    __syncthreads();
    if (threadIdx.x < N) {
        float r = buf[threadIdx.x];
        #pragma unroll
        for (int w = 1; w < 8; w++) r += buf[w*N + threadIdx.x];
        buf[8*N + threadIdx.x] = r;
    }
    __syncthreads();
    #pragma unroll
    for (int n = 0; n < N; n++) vals[n] = buf[8*N + n];
}

// ============================================================
// K2: per-column q + softmax over s; scratch reads evict-first
// so the g plane stays L2-resident for K3.
// ============================================================
__global__ __launch_bounds__(256) void k2_kernel(const float* __restrict__ Wq)
{
    __shared__ float buf[9*16];
    __shared__ float swq[64];
    int tid = threadIdx.x;
    int i = blockIdx.x;
    if (tid < 64) swq[tid] = Wq[tid];

    float part[9];
    #pragma unroll
    for (int c = 0; c < 9; c++) part[c] = 0.f;
    if (tid < SBLK) {
        const float* p = g_qpart + ((size_t)tid*II + i)*9;
        #pragma unroll
        for (int c = 0; c < 9; c++) part[c] = __ldcs(p + c);
    }
    block_sum<9>(part, buf);

    float inv = 1.f/(part[8] + 1e-5f);
    float q[8];
    #pragma unroll
    for (int h = 0; h < 8; h++) {
        float s = 0.f;
        #pragma unroll
        for (int c = 0; c < 8; c++) s += (part[c]*inv)*swq[c*8 + h];
        q[h] = s;
    }

    const __half2* kwp = g_kw + (size_t)i*SS + tid*16;
    const float*   vp  = g_v  + (size_t)i*SS + tid*16;

    float so[16];
    #pragma unroll
    for (int n = 0; n < 16; n++) so[n] = 0.f;

    #pragma unroll
    for (int g = 0; g < 4; g++) {
        uint4 kw4 = __ldcs(reinterpret_cast<const uint4*>(kwp) + g);
        float4 vq = __ldcs(reinterpret_cast<const float4*>(vp) + g);
        unsigned kwu[4] = {kw4.x, kw4.y, kw4.z, kw4.w};
        float vv[4] = {vq.x, vq.y, vq.z, vq.w};
        #pragma unroll
        for (int e = 0; e < 4; e++) {
            float2 kw = __half22float2(*reinterpret_cast<__half2*>(&kwu[e]));
            float kk = kw.x, w = kw.y;
            #pragma unroll
            for (int h = 0; h < 8; h++) {
                float ex = w * __expf(q[h]*kk);
                so[h]   += ex;
                so[8+h] = fmaf(ex, vv[e], so[8+h]);
            }
        }
    }
    block_sum<16>(so, buf);

    if (tid < 8) g_o[(size_t)i*8 + tid] = so[8+tid] / so[tid];
}

// ============================================================
// K3: out = (oh .* g) @ Wo + bo.
// ============================================================
__global__ __launch_bounds__(256) void k3_kernel(
    const float* __restrict__ Wo, const float* __restrict__ bo,
    float* __restrict__ out)
{
    __shared__ ulonglong2 sWO[8][4];
    __shared__ u64 sBO[8];

    int tid = threadIdx.x;
    if (tid < 32) {
        int h = tid >> 2, cp = tid & 3;
        float w0 = Wo[h*8 + 2*cp], w1 = Wo[h*8 + 2*cp+1];
        sWO[h][cp] = make_ulonglong2(pk2(w0,w0), pk2(w1,w1));
    } else if (tid < 40) {
        int c = tid - 32;
        sBO[c] = pk2(bo[c], bo[c]);
    }

    int il = tid & 31, wp = tid >> 5;
    int i  = blockIdx.x*32 + il;
    int s0 = (gridDim.y - 1 - blockIdx.y)*32;   // tail-first
    int sb = s0 + wp*4;

    float oh[8];
    {
        const float4* po = reinterpret_cast<const float4*>(g_o + (size_t)i*8);
        float4 a = po[0], b4 = po[1];
        oh[0]=a.x; oh[1]=a.y; oh[2]=a.z; oh[3]=a.w;
        oh[4]=b4.x; oh[5]=b4.y; oh[6]=b4.z; oh[7]=b4.w;
    }

    uint4 G[4];
    #pragma unroll
    for (int r = 0; r < 4; r++) G[r] = g_g[(size_t)(sb+r)*II + i];
    __syncthreads();

    float tf[4][8];
    #pragma unroll
    for (int r = 0; r < 4; r++) {
        unsigned uu[4] = {G[r].x, G[r].y, G[r].z, G[r].w};
        #pragma unroll
        for (int j = 0; j < 4; j++) {
            float2 f = __half22float2(*reinterpret_cast<__half2*>(&uu[j]));
            tf[r][2*j]   = oh[2*j]   * f.x;
            tf[r][2*j+1] = oh[2*j+1] * f.y;
        }
    }
    u64 th[2][8];
    #pragma unroll
    for (int p = 0; p < 2; p++)
        #pragma unroll
        for (int h = 0; h < 8; h++) th[p][h] = pk2(tf[2*p][h], tf[2*p+1][h]);

    u64 acc[2][8];
    #pragma unroll
    for (int c = 0; c < 8; c++) {
        u64 b = sBO[c];
        acc[0][c] = b; acc[1][c] = b;
    }

    #pragma unroll
    for (int h = 0; h < 8; h++) {
        ulonglong2 o0 = sWO[h][0], o1 = sWO[h][1], o2 = sWO[h][2], o3 = sWO[h][3];
        #pragma unroll
        for (int p = 0; p < 2; p++) {
            acc[p][0] = f2fma(th[p][h], o0.x, acc[p][0]);
            acc[p][1] = f2fma(th[p][h], o0.y, acc[p][1]);
            acc[p][2] = f2fma(th[p][h], o1.x, acc[p][2]);
            acc[p][3] = f2fma(th[p][h], o1.y, acc[p][3]);
            acc[p][4] = f2fma(th[p][h], o2.x, acc[p][4]);
            acc[p][5] = f2fma(th[p][h], o2.y, acc[p][5]);
            acc[p][6] = f2fma(th[p][h], o3.x, acc[p][6]);
            acc[p][7] = f2fma(th[p][h], o3.y, acc[p][7]);
        }
    }

    #pragma unroll
    for (int p = 0; p < 2; p++) {
        float y0[8], y1[8];
        #pragma unroll
        for (int c = 0; c < 8; c++) un2(acc[p][c], y0[c], y1[c]);
        size_t off0 = ((size_t)(sb+2*p)*II + i)*CC;
        size_t off1 = ((size_t)(sb+2*p+1)*II + i)*CC;
        __stcs(reinterpret_cast<float4*>(out + off0),     make_float4(y0[0],y0[1],y0[2],y0[3]));
        __stcs(reinterpret_cast<float4*>(out + off0 + 4), make_float4(y0[4],y0[5],y0[6],y0[7]));
        __stcs(reinterpret_cast<float4*>(out + off1),     make_float4(y1[0],y1[1],y1[2],y1[3]));
        __stcs(reinterpret_cast<float4*>(out + off1 + 4), make_float4(y1[4],y1[5],y1[6],y1[7]));
    }
}

// ============================================================
extern "C" void kernel_launch(void* const* d_in, const int* in_sizes, int n_in,
                              void* d_out, int out_size)
{
    const float* m     = (const float*)d_in[0];
    const float* mask  = (const float*)d_in[1];
    const float* gamma = (const float*)d_in[2];
    const float* beta  = (const float*)d_in[3];
    const float* Wq    = (const float*)d_in[4];
    const float* Wk    = (const float*)d_in[5];
    const float* Wv    = (const float*)d_in[6];
    const float* Wg    = (const float*)d_in[7];
    const float* bg    = (const float*)d_in[8];
    const float* Wo    = (const float*)d_in[9];
    const float* bo    = (const float*)d_in[10];
    float* out = (float*)d_out;

    dim3 g1(II/32, SS/32);
    k1_kernel<<<g1, 256>>>(m, mask, gamma, beta, Wk, Wv, Wg, bg);
    k2_kernel<<<II, 256>>>(Wq);
    dim3 g3(II/32, SS/32);
    k3_kernel<<<g3, 256>>>(Wo, bo, out);
}

// round 9
// speedup vs baseline: 1.8561x; 1.1664x over previous
#include <cuda_runtime.h>
#include <cuda_fp16.h>
#include <math_constants.h>

#define SS 4096
#define II 1024
#define CC 8
#define HH 8
#define SBLK (SS/32)

typedef unsigned long long u64;

// ---- scratch ----
__device__ __half2 g_kw[(size_t)II*SS];       // (k, w=exp(bias)) per [i][s]
__device__ float   g_v [(size_t)II*SS];       // v [i][s]
__device__ uint4   g_mn[(size_t)SS*II];       // normalized mn: 8 fp16 per (s,i)
__device__ float   g_qpart[(size_t)SBLK*II*9];
__device__ float   g_o[(size_t)II*HH];

// ---- helpers ----
__device__ __forceinline__ u64 pk2(float lo, float hi){u64 r;asm("mov.b64 %0,{%1,%2};":"=l"(r):"f"(lo),"f"(hi));return r;}
__device__ __forceinline__ void un2(u64 v, float&a, float&b){asm("mov.b64 {%0,%1},%2;":"=f"(a),"=f"(b):"l"(v));}
__device__ __forceinline__ u64 f2fma(u64 a,u64 b,u64 c){u64 d;asm("fma.rn.f32x2 %0,%1,%2,%3;":"=l"(d):"l"(a),"l"(b),"l"(c));return d;}
__device__ __forceinline__ u64 f2add(u64 a,u64 b){u64 d;asm("add.rn.f32x2 %0,%1,%2;":"=l"(d):"l"(a),"l"(b));return d;}
__device__ __forceinline__ u64 f2mul(u64 a,u64 b){u64 d;asm("mul.rn.f32x2 %0,%1,%2;":"=l"(d):"l"(a),"l"(b));return d;}
__device__ __forceinline__ float tanha(float x){float r;asm("tanh.approx.f32 %0,%1;":"=f"(r):"f"(x));return r;}

// ============================================================
// K1: LayerNorm + (k,w)/v planes (transposed) + mn (fp16, [s][i])
//     + q-pool partials.  mn store is pure cvt+STG — no extra math.
// grid (II/32, SS/32), block 256
// ============================================================
__global__ __launch_bounds__(256,3) void k1_kernel(
    const float* __restrict__ m, const float* __restrict__ mask,
    const float* __restrict__ gamma, const float* __restrict__ beta,
    const float* __restrict__ Wk, const float* __restrict__ Wv)
{
    __shared__ float tk[32][33], tv[32][33], tw[32][33];
    __shared__ float red[3][8][33];
    __shared__ float wgt[32];
    int tid = threadIdx.x;
    if (tid < 32) {
        float v;
        if      (tid <  8) v = gamma[tid];
        else if (tid < 16) v = beta[tid-8];
        else if (tid < 24) v = Wk[tid-16];
        else               v = Wv[tid-24];
        wgt[tid] = v;
    }
    __syncthreads();

    int il = tid & 31, wp = tid >> 5;
    int i  = blockIdx.x*32 + il;
    int s0 = blockIdx.y*32;
    int sb = s0 + wp*4;

    // front-batched streaming m loads (never re-read: .cs)
    float4 A[4][2];
    #pragma unroll
    for (int r = 0; r < 4; r++) {
        const float4* p = reinterpret_cast<const float4*>(m + ((size_t)(sb+r)*II + i)*CC);
        A[r][0] = __ldcs(p); A[r][1] = __ldcs(p+1);
    }

    float qacc[8];
    #pragma unroll
    for (int c = 0; c < 8; c++) qacc[c] = 0.f;
    float macc = 0.f;

    #pragma unroll
    for (int r = 0; r < 4; r++) {
        int sl = wp*4 + r;
        float mk = __ldcs(&mask[(size_t)(sb+r)*II + i]);
        const float* x = &A[r][0].x;     // 8 contiguous floats
        float mu = 0.f;
        #pragma unroll
        for (int c = 0; c < 8; c++) mu += x[c];
        mu *= 0.125f;
        float var = 0.f;
        #pragma unroll
        for (int c = 0; c < 8; c++) { float d = x[c]-mu; var += d*d; }
        var *= 0.125f;
        float rstd = rsqrtf(var + 1e-5f);
        float kv = 0.f, vv = 0.f;
        unsigned gp[4];
        float prev;
        #pragma unroll
        for (int c = 0; c < 8; c++) {
            float mn = (x[c]-mu)*rstd*wgt[c] + wgt[8+c];
            kv += mn*wgt[16+c];
            vv += mn*wgt[24+c];
            qacc[c] += mn*mk;
            if (c & 1) {
                __half2 hh = __floats2half2_rn(prev, mn);
                gp[c>>1] = *reinterpret_cast<unsigned*>(&hh);
            } else prev = mn;
        }
        macc += mk;
        tk[il][sl] = kv;
        tv[il][sl] = vv;
        tw[il][sl] = __expf(1e9f*(mk - 1.f));
        g_mn[(size_t)(sb+r)*II + i] = make_uint4(gp[0], gp[1], gp[2], gp[3]);
    }
    __syncthreads();

    // coalesced transposed writeout (scratch stays L2-resident for K2)
    {
        int ir = tid >> 3, sj = (tid & 7)*4;
        size_t off = (size_t)(blockIdx.x*32 + ir)*SS + s0 + sj;
        *reinterpret_cast<float4*>(g_v + off) =
            make_float4(tv[ir][sj], tv[ir][sj+1], tv[ir][sj+2], tv[ir][sj+3]);
        __half2 h0 = __floats2half2_rn(tk[ir][sj],   tw[ir][sj]);
        __half2 h1 = __floats2half2_rn(tk[ir][sj+1], tw[ir][sj+1]);
        __half2 h2 = __floats2half2_rn(tk[ir][sj+2], tw[ir][sj+2]);
        __half2 h3 = __floats2half2_rn(tk[ir][sj+3], tw[ir][sj+3]);
        uint4 u;
        u.x = *reinterpret_cast<unsigned int*>(&h0);
        u.y = *reinterpret_cast<unsigned int*>(&h1);
        u.z = *reinterpret_cast<unsigned int*>(&h2);
        u.w = *reinterpret_cast<unsigned int*>(&h3);
        *reinterpret_cast<uint4*>(g_kw + off) = u;
    }

    #pragma unroll
    for (int r = 0; r < 3; r++) {
        __syncthreads();
        #pragma unroll
        for (int gch = 0; gch < 3; gch++) {
            int c = r*3 + gch;
            red[gch][wp][il] = (c < 8) ? qacc[c] : macc;
        }
        __syncthreads();
        if (wp < 3) {
            int c = r*3 + wp;
            float sum = 0.f;
            #pragma unroll
            for (int w = 0; w < 8; w++) sum += red[wp][w][il];
            g_qpart[((size_t)blockIdx.y*II + i)*9 + c] = sum;
        }
    }
}

// ---------------- block reduction ----------------
__device__ __forceinline__ float warp_sum(float v) {
    #pragma unroll
    for (int o = 16; o; o >>= 1) v += __shfl_xor_sync(0xffffffffu, v, o);
    return v;
}
template<int N>
__device__ __forceinline__ void block_sum(float* vals, float* buf) {
    int lane = threadIdx.x & 31, wp = threadIdx.x >> 5;
    __syncthreads();
    #pragma unroll
    for (int n = 0; n < N; n++) {
        float v = warp_sum(vals[n]);
        if (lane == 0) buf[wp*N + n] = v;
    }
    __syncthreads();
    if (threadIdx.x < N) {
        float r = buf[threadIdx.x];
        #pragma unroll
        for (int w = 1; w < 8; w++) r += buf[w*N + threadIdx.x];
        buf[8*N + threadIdx.x] = r;
    }
    __syncthreads();
    #pragma unroll
    for (int n = 0; n < N; n++) vals[n] = buf[8*N + n];
}

// ============================================================
// K2: per-column q + softmax over s; scratch reads evict-first
// so the mn plane stays L2-resident for K3.
// ============================================================
__global__ __launch_bounds__(256) void k2_kernel(const float* __restrict__ Wq)
{
    __shared__ float buf[9*16];
    __shared__ float swq[64];
    int tid = threadIdx.x;
    int i = blockIdx.x;
    if (tid < 64) swq[tid] = Wq[tid];

    float part[9];
    #pragma unroll
    for (int c = 0; c < 9; c++) part[c] = 0.f;
    if (tid < SBLK) {
        const float* p = g_qpart + ((size_t)tid*II + i)*9;
        #pragma unroll
        for (int c = 0; c < 9; c++) part[c] = __ldcs(p + c);
    }
    block_sum<9>(part, buf);

    float inv = 1.f/(part[8] + 1e-5f);
    float q[8];
    #pragma unroll
    for (int h = 0; h < 8; h++) {
        float s = 0.f;
        #pragma unroll
        for (int c = 0; c < 8; c++) s += (part[c]*inv)*swq[c*8 + h];
        q[h] = s;
    }

    const __half2* kwp = g_kw + (size_t)i*SS + tid*16;
    const float*   vp  = g_v  + (size_t)i*SS + tid*16;

    float so[16];
    #pragma unroll
    for (int n = 0; n < 16; n++) so[n] = 0.f;

    #pragma unroll
    for (int g = 0; g < 4; g++) {
        uint4 kw4 = __ldcs(reinterpret_cast<const uint4*>(kwp) + g);
        float4 vq = __ldcs(reinterpret_cast<const float4*>(vp) + g);
        unsigned kwu[4] = {kw4.x, kw4.y, kw4.z, kw4.w};
        float vv[4] = {vq.x, vq.y, vq.z, vq.w};
        #pragma unroll
        for (int e = 0; e < 4; e++) {
            float2 kw = __half22float2(*reinterpret_cast<__half2*>(&kwu[e]));
            float kk = kw.x, w = kw.y;
            #pragma unroll
            for (int h = 0; h < 8; h++) {
                float ex = w * __expf(q[h]*kk);
                so[h]   += ex;
                so[8+h] = fmaf(ex, vv[e], so[8+h]);
            }
        }
    }
    block_sum<16>(so, buf);

    if (tid < 8) g_o[(size_t)i*8 + tid] = so[8+tid] / so[tid];
}

// ============================================================
// K3: gate = sigmoid(mn@Wg+bg) from fp16 mn (no LayerNorm!),
//     out = (oh .* gate) @ Wo + bo.  f32x2 over row pairs.
// grid (II/32, SS/32), block 256, 4 rows/thread
// ============================================================
__global__ __launch_bounds__(256) void k3_kernel(
    const float* __restrict__ Wg, const float* __restrict__ bg,
    const float* __restrict__ Wo, const float* __restrict__ bo,
    float* __restrict__ out)
{
    __shared__ ulonglong2 sWG[8][4];   // [h][cpair]: dup 0.5*Wg[c][h]
    __shared__ u64 sCB[8];             // dup 0.5*bg[h]
    __shared__ ulonglong2 sWO[8][4];   // [h][cpair]: dup Wo[h][c]
    __shared__ u64 sBO[8];             // dup bo[c]

    int tid = threadIdx.x;
    if (tid < 32) {
        int h = tid >> 2, cp = tid & 3;
        float w0 = 0.5f*Wg[(2*cp)*8 + h];
        float w1 = 0.5f*Wg[(2*cp+1)*8 + h];
        sWG[h][cp] = make_ulonglong2(pk2(w0,w0), pk2(w1,w1));
    } else if (tid < 64) {
        int t = tid - 32; int h = t >> 2, cp = t & 3;
        float w0 = Wo[h*8 + 2*cp], w1 = Wo[h*8 + 2*cp+1];
        sWO[h][cp] = make_ulonglong2(pk2(w0,w0), pk2(w1,w1));
    } else if (tid < 72) {
        int h = tid - 64;
        float c = 0.5f*bg[h];
        sCB[h] = pk2(c, c);
    } else if (tid < 80) {
        int c = tid - 72;
        sBO[c] = pk2(bo[c], bo[c]);
    }

    int il = tid & 31, wp = tid >> 5;
    int i  = blockIdx.x*32 + il;
    int s0 = (gridDim.y - 1 - blockIdx.y)*32;   // tail-first: ride K1's L2 tail
    int sb = s0 + wp*4;

    float oh2[8];   // 0.5*oh
    {
        const float4* po = reinterpret_cast<const float4*>(g_o + (size_t)i*8);
        float4 a = po[0], b4 = po[1];
        oh2[0]=0.5f*a.x; oh2[1]=0.5f*a.y; oh2[2]=0.5f*a.z; oh2[3]=0.5f*a.w;
        oh2[4]=0.5f*b4.x; oh2[5]=0.5f*b4.y; oh2[6]=0.5f*b4.z; oh2[7]=0.5f*b4.w;
    }

    uint4 G[4];
    #pragma unroll
    for (int r = 0; r < 4; r++) G[r] = g_mn[(size_t)(sb+r)*II + i];
    __syncthreads();

    #pragma unroll
    for (int p = 0; p < 2; p++) {
        // unpack two rows into f32x2 channel pairs
        u64 xp[8];
        {
            unsigned ua[4] = {G[2*p].x, G[2*p].y, G[2*p].z, G[2*p].w};
            unsigned ub[4] = {G[2*p+1].x, G[2*p+1].y, G[2*p+1].z, G[2*p+1].w};
            #pragma unroll
            for (int j = 0; j < 4; j++) {
                float2 fa = __half22float2(*reinterpret_cast<__half2*>(&ua[j]));
                float2 fb = __half22float2(*reinterpret_cast<__half2*>(&ub[j]));
                xp[2*j]   = pk2(fa.x, fb.x);
                xp[2*j+1] = pk2(fa.y, fb.y);
            }
        }

        u64 acc[8];
        #pragma unroll
        for (int c = 0; c < 8; c++) acc[c] = sBO[c];

        #pragma unroll
        for (int h = 0; h < 8; h++) {
            ulonglong2 w0 = sWG[h][0], w1 = sWG[h][1], w2 = sWG[h][2], w3 = sWG[h][3];
            u64 dot = f2mul(xp[0], w0.x);
            dot = f2fma(xp[1], w0.y, dot);
            dot = f2fma(xp[2], w1.x, dot);
            dot = f2fma(xp[3], w1.y, dot);
            dot = f2fma(xp[4], w2.x, dot);
            dot = f2fma(xp[5], w2.y, dot);
            dot = f2fma(xp[6], w3.x, dot);
            dot = f2fma(xp[7], w3.y, dot);
            u64 z2 = f2add(dot, sCB[h]);        // 0.5*z
            float za, zb; un2(z2, za, zb);
            float t0 = fmaf(oh2[h], tanha(za), oh2[h]);  // oh*sigmoid(z)
            float t1 = fmaf(oh2[h], tanha(zb), oh2[h]);
            u64 th = pk2(t0, t1);
            ulonglong2 o0 = sWO[h][0], o1 = sWO[h][1], o2 = sWO[h][2], o3 = sWO[h][3];
            acc[0] = f2fma(th, o0.x, acc[0]);
            acc[1] = f2fma(th, o0.y, acc[1]);
            acc[2] = f2fma(th, o1.x, acc[2]);
            acc[3] = f2fma(th, o1.y, acc[3]);
            acc[4] = f2fma(th, o2.x, acc[4]);
            acc[5] = f2fma(th, o2.y, acc[5]);
            acc[6] = f2fma(th, o3.x, acc[6]);
            acc[7] = f2fma(th, o3.y, acc[7]);
        }

        float y0[8], y1[8];
        #pragma unroll
        for (int c = 0; c < 8; c++) un2(acc[c], y0[c], y1[c]);
        size_t off0 = ((size_t)(sb+2*p)*II + i)*CC;
        size_t off1 = ((size_t)(sb+2*p+1)*II + i)*CC;
        __stcs(reinterpret_cast<float4*>(out + off0),     make_float4(y0[0],y0[1],y0[2],y0[3]));
        __stcs(reinterpret_cast<float4*>(out + off0 + 4), make_float4(y0[4],y0[5],y0[6],y0[7]));
        __stcs(reinterpret_cast<float4*>(out + off1),     make_float4(y1[0],y1[1],y1[2],y1[3]));
        __stcs(reinterpret_cast<float4*>(out + off1 + 4), make_float4(y1[4],y1[5],y1[6],y1[7]));
    }
}

// ============================================================
extern "C" void kernel_launch(void* const* d_in, const int* in_sizes, int n_in,
                              void* d_out, int out_size)
{
    const float* m     = (const float*)d_in[0];
    const float* mask  = (const float*)d_in[1];
    const float* gamma = (const float*)d_in[2];
    const float* beta  = (const float*)d_in[3];
    const float* Wq    = (const float*)d_in[4];
    const float* Wk    = (const float*)d_in[5];
    const float* Wv    = (const float*)d_in[6];
    const float* Wg    = (const float*)d_in[7];
    const float* bg    = (const float*)d_in[8];
    const float* Wo    = (const float*)d_in[9];
    const float* bo    = (const float*)d_in[10];
    float* out = (float*)d_out;

    dim3 g1(II/32, SS/32);
    k1_kernel<<<g1, 256>>>(m, mask, gamma, beta, Wk, Wv);
    k2_kernel<<<II, 256>>>(Wq);
    dim3 g3(II/32, SS/32);
    k3_kernel<<<g3, 256>>>(Wg, bg, Wo, bo, out);
}

// round 10
// speedup vs baseline: 1.8567x; 1.0003x over previous
#include <cuda_runtime.h>
#include <cuda_fp16.h>
#include <math_constants.h>

#define SS 4096
#define II 1024
#define CC 8
#define HH 8
#define SBLK (SS/32)

typedef unsigned long long u64;

// ---- scratch ----
__device__ __half2 g_kw[(size_t)II*SS];       // (k, w=exp(bias)) per [i][s]
__device__ float   g_v [(size_t)II*SS];       // v [i][s]
__device__ uint4   g_mn[(size_t)SS*II];       // normalized mn: 8 fp16 per (s,i)
__device__ float   g_qpart[(size_t)SBLK*II*9];
__device__ float   g_o[(size_t)II*HH];

// ---- helpers ----
__device__ __forceinline__ u64 pk2(float lo, float hi){u64 r;asm("mov.b64 %0,{%1,%2};":"=l"(r):"f"(lo),"f"(hi));return r;}
__device__ __forceinline__ void un2(u64 v, float&a, float&b){asm("mov.b64 {%0,%1},%2;":"=f"(a),"=f"(b):"l"(v));}
__device__ __forceinline__ u64 f2fma(u64 a,u64 b,u64 c){u64 d;asm("fma.rn.f32x2 %0,%1,%2,%3;":"=l"(d):"l"(a),"l"(b),"l"(c));return d;}
__device__ __forceinline__ u64 f2add(u64 a,u64 b){u64 d;asm("add.rn.f32x2 %0,%1,%2;":"=l"(d):"l"(a),"l"(b));return d;}
__device__ __forceinline__ u64 f2mul(u64 a,u64 b){u64 d;asm("mul.rn.f32x2 %0,%1,%2;":"=l"(d):"l"(a),"l"(b));return d;}
__device__ __forceinline__ float tanha(float x){float r;asm("tanh.approx.f32 %0,%1;":"=f"(r):"f"(x));return r;}

// ============================================================
// K1: LayerNorm + (k,w)/v planes (transposed) + mn (fp16, [s][i])
//     + q-pool partials (single-round reduction).
// grid (II/32, SS/32), block 256
// ============================================================
__global__ __launch_bounds__(256,3) void k1_kernel(
    const float* __restrict__ m, const float* __restrict__ mask,
    const float* __restrict__ gamma, const float* __restrict__ beta,
    const float* __restrict__ Wk, const float* __restrict__ Wv)
{
    __shared__ float tk[32][33], tv[32][33], tw[32][33];
    __shared__ float red2[8][32*9 + 4];
    __shared__ float wgt[32];
    int tid = threadIdx.x;
    if (tid < 32) {
        float v;
        if      (tid <  8) v = gamma[tid];
        else if (tid < 16) v = beta[tid-8];
        else if (tid < 24) v = Wk[tid-16];
        else               v = Wv[tid-24];
        wgt[tid] = v;
    }
    __syncthreads();

    int il = tid & 31, wp = tid >> 5;
    int i  = blockIdx.x*32 + il;
    int s0 = blockIdx.y*32;
    int sb = s0 + wp*4;

    // front-batched streaming m loads (never re-read: .cs)
    float4 A[4][2];
    #pragma unroll
    for (int r = 0; r < 4; r++) {
        const float4* p = reinterpret_cast<const float4*>(m + ((size_t)(sb+r)*II + i)*CC);
        A[r][0] = __ldcs(p); A[r][1] = __ldcs(p+1);
    }

    float qacc[8];
    #pragma unroll
    for (int c = 0; c < 8; c++) qacc[c] = 0.f;
    float macc = 0.f;

    #pragma unroll
    for (int r = 0; r < 4; r++) {
        int sl = wp*4 + r;
        float mk = __ldcs(&mask[(size_t)(sb+r)*II + i]);
        const float* x = &A[r][0].x;     // 8 contiguous floats
        float mu = 0.f;
        #pragma unroll
        for (int c = 0; c < 8; c++) mu += x[c];
        mu *= 0.125f;
        float var = 0.f;
        #pragma unroll
        for (int c = 0; c < 8; c++) { float d = x[c]-mu; var += d*d; }
        var *= 0.125f;
        float rstd = rsqrtf(var + 1e-5f);
        float kv = 0.f, vv = 0.f;
        unsigned gp[4];
        float prev;
        #pragma unroll
        for (int c = 0; c < 8; c++) {
            float mn = (x[c]-mu)*rstd*wgt[c] + wgt[8+c];
            kv += mn*wgt[16+c];
            vv += mn*wgt[24+c];
            qacc[c] += mn*mk;
            if (c & 1) {
                __half2 hh = __floats2half2_rn(prev, mn);
                gp[c>>1] = *reinterpret_cast<unsigned*>(&hh);
            } else prev = mn;
        }
        macc += mk;
        tk[il][sl] = kv;
        tv[il][sl] = vv;
        tw[il][sl] = __expf(1e9f*(mk - 1.f));
        g_mn[(size_t)(sb+r)*II + i] = make_uint4(gp[0], gp[1], gp[2], gp[3]);
    }
    __syncthreads();

    // coalesced transposed writeout (scratch stays L2-resident for K2)
    {
        int ir = tid >> 3, sj = (tid & 7)*4;
        size_t off = (size_t)(blockIdx.x*32 + ir)*SS + s0 + sj;
        *reinterpret_cast<float4*>(g_v + off) =
            make_float4(tv[ir][sj], tv[ir][sj+1], tv[ir][sj+2], tv[ir][sj+3]);
        __half2 h0 = __floats2half2_rn(tk[ir][sj],   tw[ir][sj]);
        __half2 h1 = __floats2half2_rn(tk[ir][sj+1], tw[ir][sj+1]);
        __half2 h2 = __floats2half2_rn(tk[ir][sj+2], tw[ir][sj+2]);
        __half2 h3 = __floats2half2_rn(tk[ir][sj+3], tw[ir][sj+3]);
        uint4 u;
        u.x = *reinterpret_cast<unsigned int*>(&h0);
        u.y = *reinterpret_cast<unsigned int*>(&h1);
        u.z = *reinterpret_cast<unsigned int*>(&h2);
        u.w = *reinterpret_cast<unsigned int*>(&h3);
        *reinterpret_cast<uint4*>(g_kw + off) = u;
    }

    // single-round q-pool reduction: warp partials -> 3 warps finish
    #pragma unroll
    for (int c = 0; c < 8; c++) red2[wp][il*9 + c] = qacc[c];
    red2[wp][il*9 + 8] = macc;
    __syncthreads();
    if (wp < 3) {
        #pragma unroll
        for (int j = 0; j < 3; j++) {
            int c = wp*3 + j;
            float sum = 0.f;
            #pragma unroll
            for (int w = 0; w < 8; w++) sum += red2[w][il*9 + c];
            g_qpart[((size_t)blockIdx.y*II + i)*9 + c] = sum;
        }
    }
}

// ---------------- block reduction ----------------
__device__ __forceinline__ float warp_sum(float v) {
    #pragma unroll
    for (int o = 16; o; o >>= 1) v += __shfl_xor_sync(0xffffffffu, v, o);
    return v;
}
template<int N>
__device__ __forceinline__ void block_sum(float* vals, float* buf) {
    int lane = threadIdx.x & 31, wp = threadIdx.x >> 5;
    __syncthreads();
    #pragma unroll
    for (int n = 0; n < N; n++) {
        float v = warp_sum(vals[n]);
        if (lane == 0) buf[wp*N + n] = v;
    }
    __syncthreads();
    if (threadIdx.x < N) {
        float r = buf[threadIdx.x];
        #pragma unroll
        for (int w = 1; w < 8; w++) r += buf[w*N + threadIdx.x];
        buf[8*N + threadIdx.x] = r;
    }
    __syncthreads();
    #pragma unroll
    for (int n = 0; n < N; n++) vals[n] = buf[8*N + n];
}

// ============================================================
// K2: per-column q + softmax over s; scratch reads evict-first
// so the mn plane stays L2-resident for K3.
// ============================================================
__global__ __launch_bounds__(256) void k2_kernel(const float* __restrict__ Wq)
{
    __shared__ float buf[9*16];
    __shared__ float swq[64];
    int tid = threadIdx.x;
    int i = blockIdx.x;
    if (tid < 64) swq[tid] = Wq[tid];

    float part[9];
    #pragma unroll
    for (int c = 0; c < 9; c++) part[c] = 0.f;
    if (tid < SBLK) {
        const float* p = g_qpart + ((size_t)tid*II + i)*9;
        #pragma unroll
        for (int c = 0; c < 9; c++) part[c] = __ldcs(p + c);
    }
    block_sum<9>(part, buf);

    float inv = 1.f/(part[8] + 1e-5f);
    float q[8];
    #pragma unroll
    for (int h = 0; h < 8; h++) {
        float s = 0.f;
        #pragma unroll
        for (int c = 0; c < 8; c++) s += (part[c]*inv)*swq[c*8 + h];
        q[h] = s;
    }

    const __half2* kwp = g_kw + (size_t)i*SS + tid*16;
    const float*   vp  = g_v  + (size_t)i*SS + tid*16;

    float so[16];
    #pragma unroll
    for (int n = 0; n < 16; n++) so[n] = 0.f;

    #pragma unroll
    for (int g = 0; g < 4; g++) {
        uint4 kw4 = __ldcs(reinterpret_cast<const uint4*>(kwp) + g);
        float4 vq = __ldcs(reinterpret_cast<const float4*>(vp) + g);
        unsigned kwu[4] = {kw4.x, kw4.y, kw4.z, kw4.w};
        float vv[4] = {vq.x, vq.y, vq.z, vq.w};
        #pragma unroll
        for (int e = 0; e < 4; e++) {
            float2 kw = __half22float2(*reinterpret_cast<__half2*>(&kwu[e]));
            float kk = kw.x, w = kw.y;
            #pragma unroll
            for (int h = 0; h < 8; h++) {
                float ex = w * __expf(q[h]*kk);
                so[h]   += ex;
                so[8+h] = fmaf(ex, vv[e], so[8+h]);
            }
        }
    }
    block_sum<16>(so, buf);

    if (tid < 8) g_o[(size_t)i*8 + tid] = so[8+tid] / so[tid];
}

// ============================================================
// K3: gate = sigmoid(mn@Wg+bg) from fp16 mn, out = (oh.*g)@Wo+bo.
// h-OUTER loop: each head's weights loaded once, applied to both
// row pairs -> 64 LDS.128/thread instead of 128.
// grid (II/32, SS/32), block 256, 4 rows/thread
// ============================================================
__global__ __launch_bounds__(256) void k3_kernel(
    const float* __restrict__ Wg, const float* __restrict__ bg,
    const float* __restrict__ Wo, const float* __restrict__ bo,
    float* __restrict__ out)
{
    __shared__ ulonglong2 sWG[8][4];   // [h][cpair]: dup 0.5*Wg[c][h]
    __shared__ u64 sCB[8];             // dup 0.5*bg[h]
    __shared__ ulonglong2 sWO[8][4];   // [h][cpair]: dup Wo[h][c]
    __shared__ u64 sBO[8];             // dup bo[c]

    int tid = threadIdx.x;
    if (tid < 32) {
        int h = tid >> 2, cp = tid & 3;
        float w0 = 0.5f*Wg[(2*cp)*8 + h];
        float w1 = 0.5f*Wg[(2*cp+1)*8 + h];
        sWG[h][cp] = make_ulonglong2(pk2(w0,w0), pk2(w1,w1));
    } else if (tid < 64) {
        int t = tid - 32; int h = t >> 2, cp = t & 3;
        float w0 = Wo[h*8 + 2*cp], w1 = Wo[h*8 + 2*cp+1];
        sWO[h][cp] = make_ulonglong2(pk2(w0,w0), pk2(w1,w1));
    } else if (tid < 72) {
        int h = tid - 64;
        float c = 0.5f*bg[h];
        sCB[h] = pk2(c, c);
    } else if (tid < 80) {
        int c = tid - 72;
        sBO[c] = pk2(bo[c], bo[c]);
    }

    int il = tid & 31, wp = tid >> 5;
    int i  = blockIdx.x*32 + il;
    int s0 = (gridDim.y - 1 - blockIdx.y)*32;   // tail-first: ride K1's L2 tail
    int sb = s0 + wp*4;

    float oh2[8];   // 0.5*oh
    {
        const float4* po = reinterpret_cast<const float4*>(g_o + (size_t)i*8);
        float4 a = po[0], b4 = po[1];
        oh2[0]=0.5f*a.x; oh2[1]=0.5f*a.y; oh2[2]=0.5f*a.z; oh2[3]=0.5f*a.w;
        oh2[4]=0.5f*b4.x; oh2[5]=0.5f*b4.y; oh2[6]=0.5f*b4.z; oh2[7]=0.5f*b4.w;
    }

    uint4 G[4];
    #pragma unroll
    for (int r = 0; r < 4; r++) G[r] = g_mn[(size_t)(sb+r)*II + i];
    __syncthreads();

    // unpack all 4 rows into 2 f32x2 pair-sets
    u64 xp[2][8];
    #pragma unroll
    for (int p = 0; p < 2; p++) {
        unsigned ua[4] = {G[2*p].x, G[2*p].y, G[2*p].z, G[2*p].w};
        unsigned ub[4] = {G[2*p+1].x, G[2*p+1].y, G[2*p+1].z, G[2*p+1].w};
        #pragma unroll
        for (int j = 0; j < 4; j++) {
            float2 fa = __half22float2(*reinterpret_cast<__half2*>(&ua[j]));
            float2 fb = __half22float2(*reinterpret_cast<__half2*>(&ub[j]));
            xp[p][2*j]   = pk2(fa.x, fb.x);
            xp[p][2*j+1] = pk2(fa.y, fb.y);
        }
    }

    u64 acc[2][8];
    #pragma unroll
    for (int c = 0; c < 8; c++) {
        u64 b = sBO[c];
        acc[0][c] = b; acc[1][c] = b;
    }

    #pragma unroll
    for (int h = 0; h < 8; h++) {
        ulonglong2 w0 = sWG[h][0], w1 = sWG[h][1], w2 = sWG[h][2], w3 = sWG[h][3];
        ulonglong2 o0 = sWO[h][0], o1 = sWO[h][1], o2 = sWO[h][2], o3 = sWO[h][3];
        u64 cb = sCB[h];
        #pragma unroll
        for (int p = 0; p < 2; p++) {
            u64 dot = f2mul(xp[p][0], w0.x);
            dot = f2fma(xp[p][1], w0.y, dot);
            dot = f2fma(xp[p][2], w1.x, dot);
            dot = f2fma(xp[p][3], w1.y, dot);
            dot = f2fma(xp[p][4], w2.x, dot);
            dot = f2fma(xp[p][5], w2.y, dot);
            dot = f2fma(xp[p][6], w3.x, dot);
            dot = f2fma(xp[p][7], w3.y, dot);
            u64 z2 = f2add(dot, cb);                    // 0.5*z
            float za, zb; un2(z2, za, zb);
            float t0 = fmaf(oh2[h], tanha(za), oh2[h]); // oh*sigmoid(z)
            float t1 = fmaf(oh2[h], tanha(zb), oh2[h]);
            u64 th = pk2(t0, t1);
            acc[p][0] = f2fma(th, o0.x, acc[p][0]);
            acc[p][1] = f2fma(th, o0.y, acc[p][1]);
            acc[p][2] = f2fma(th, o1.x, acc[p][2]);
            acc[p][3] = f2fma(th, o1.y, acc[p][3]);
            acc[p][4] = f2fma(th, o2.x, acc[p][4]);
            acc[p][5] = f2fma(th, o2.y, acc[p][5]);
            acc[p][6] = f2fma(th, o3.x, acc[p][6]);
            acc[p][7] = f2fma(th, o3.y, acc[p][7]);
        }
    }

    #pragma unroll
    for (int p = 0; p < 2; p++) {
        float y0[8], y1[8];
        #pragma unroll
        for (int c = 0; c < 8; c++) un2(acc[p][c], y0[c], y1[c]);
        size_t off0 = ((size_t)(sb+2*p)*II + i)*CC;
        size_t off1 = ((size_t)(sb+2*p+1)*II + i)*CC;
        __stcs(reinterpret_cast<float4*>(out + off0),     make_float4(y0[0],y0[1],y0[2],y0[3]));
        __stcs(reinterpret_cast<float4*>(out + off0 + 4), make_float4(y0[4],y0[5],y0[6],y0[7]));
        __stcs(reinterpret_cast<float4*>(out + off1),     make_float4(y1[0],y1[1],y1[2],y1[3]));
        __stcs(reinterpret_cast<float4*>(out + off1 + 4), make_float4(y1[4],y1[5],y1[6],y1[7]));
    }
}

// ============================================================
extern "C" void kernel_launch(void* const* d_in, const int* in_sizes, int n_in,
                              void* d_out, int out_size)
{
    const float* m     = (const float*)d_in[0];
    const float* mask  = (const float*)d_in[1];
    const float* gamma = (const float*)d_in[2];
    const float* beta  = (const float*)d_in[3];
    const float* Wq    = (const float*)d_in[4];
    const float* Wk    = (const float*)d_in[5];
    const float* Wv    = (const float*)d_in[6];
    const float* Wg    = (const float*)d_in[7];
    const float* bg    = (const float*)d_in[8];
    const float* Wo    = (const float*)d_in[9];
    const float* bo    = (const float*)d_in[10];
    float* out = (float*)d_out;

    dim3 g1(II/32, SS/32);
    k1_kernel<<<g1, 256>>>(m, mask, gamma, beta, Wk, Wv);
    k2_kernel<<<II, 256>>>(Wq);
    dim3 g3(II/32, SS/32);
    k3_kernel<<<g3, 256>>>(Wg, bg, Wo, bo, out);
}